// round 6
// baseline (speedup 1.0000x reference)
#include <cuda_runtime.h>
#include <cstdint>

// Problem constants
constexpr int Hd = 1024;   // hidden
constexpr int Ff = 4096;   // intermediate
constexpr int NE = 8;      // experts
constexpr int NT = 2048;   // tokens
constexpr int NA = 2 * NT; // assignments (top-2)

// ---------------- device scratch (no allocations allowed) ----------------
__device__ int   g_cnt[NE];
__device__ int   g_tok[NE][NT];
__device__ float g_wt[NE][NT];
__device__ int   g_slot[NE][NT];
__device__ float g_h[(size_t)NA * Ff];   // 64 MB fp32 intermediate, row = tok*2+slot
__device__ float g_sbuf[2 * NT * Hd];    // per-rank-slot output buffers

// ---------------- helpers ----------------
__device__ __forceinline__ float f2tf(float x) {
    unsigned u;
    asm("cvt.rna.tf32.f32 %0, %1;" : "=r"(u) : "f"(x));
    return __uint_as_float(u);
}
__device__ __forceinline__ float4 tf4(float4 v) {
    return make_float4(f2tf(v.x), f2tf(v.y), f2tf(v.z), f2tf(v.w));
}
__device__ __forceinline__ void mma8(float c[4], const unsigned a[4], const unsigned b[2]) {
    asm volatile(
        "mma.sync.aligned.m16n8k8.row.col.f32.tf32.tf32.f32 "
        "{%0,%1,%2,%3},{%4,%5,%6,%7},{%8,%9},{%0,%1,%2,%3};"
        : "+f"(c[0]), "+f"(c[1]), "+f"(c[2]), "+f"(c[3])
        : "r"(a[0]), "r"(a[1]), "r"(a[2]), "r"(a[3]), "r"(b[0]), "r"(b[1]));
}

// ---------------- small kernels ----------------
__global__ void zero_kernel() {
    if (threadIdx.x < NE) g_cnt[threadIdx.x] = 0;
}

// One warp per token: logits -> softmax -> top-2 -> softmax of the two PROBS.
__global__ void router_kernel(const float* __restrict__ x, const float* __restrict__ gw) {
    int tok  = blockIdx.x * 8 + (threadIdx.x >> 5);
    int lane = threadIdx.x & 31;
    if (tok >= NT) return;
    const float* xr = x + (size_t)tok * Hd;

    float acc[NE];
#pragma unroll
    for (int e = 0; e < NE; e++) acc[e] = 0.f;
    for (int i = lane; i < Hd; i += 32) {
        float xv = xr[i];
        const float* g = gw + i * NE;
#pragma unroll
        for (int e = 0; e < NE; e++) acc[e] = fmaf(xv, g[e], acc[e]);
    }
#pragma unroll
    for (int e = 0; e < NE; e++) {
#pragma unroll
        for (int o = 16; o > 0; o >>= 1) acc[e] += __shfl_xor_sync(0xffffffffu, acc[e], o);
    }
    if (lane == 0) {
        float m = acc[0];
#pragma unroll
        for (int e = 1; e < NE; e++) m = fmaxf(m, acc[e]);
        float p[NE], s = 0.f;
#pragma unroll
        for (int e = 0; e < NE; e++) { p[e] = expf(acc[e] - m); s += p[e]; }
        float inv = 1.f / s;
#pragma unroll
        for (int e = 0; e < NE; e++) p[e] *= inv;

        int i0 = 0;
#pragma unroll
        for (int e = 1; e < NE; e++) if (p[e] > p[i0]) i0 = e;
        int i1 = (i0 == 0) ? 1 : 0;
#pragma unroll
        for (int e = 0; e < NE; e++) if (e != i0 && p[e] > p[i1]) i1 = e;

        float eb = expf(p[i1] - p[i0]);       // <= 1
        float w0 = 1.f / (1.f + eb);
        float w1 = 1.f - w0;

        int s0 = atomicAdd(&g_cnt[i0], 1);
        g_tok[i0][s0] = tok; g_wt[i0][s0] = w0; g_slot[i0][s0] = 0;
        int s1 = atomicAdd(&g_cnt[i1], 1);
        g_tok[i1][s1] = tok; g_wt[i1][s1] = w1; g_slot[i1][s1] = 1;
    }
}

// ============================================================================
// GEMM1: block 128(M) x 64(N), BK=16, 128 threads, 4 warps 2x2, warp tile 64x32.
// Fused gate+up: h[aid] = silu(X Wg) * (X Wu). Smem k-interleaved p(k)=(k%4)*4+k/4,
// B stored transposed [n][p(k)] -> one LDS.128 per fragment covers both k8 steps.
// ============================================================================
__global__ void __launch_bounds__(128) gemm1_kernel(
    const float* __restrict__ x,
    const float* __restrict__ w_gate,
    const float* __restrict__ w_up)
{
    int e = blockIdx.z;
    int cnt = g_cnt[e];
    int row0 = blockIdx.y * 128;
    if (row0 >= cnt) return;
    int col0 = blockIdx.x * 64;
    const float* Bg = w_gate + (size_t)e * Hd * Ff;
    const float* Bu = w_up   + (size_t)e * Hd * Ff;

    __shared__ __align__(16) float sA[2][128][16];
    __shared__ __align__(16) float sG[2][64][16];
    __shared__ __align__(16) float sU[2][64][16];

    int t = threadIdx.x;
    int lane = t & 31, warp = t >> 5;
    int wm = warp >> 1, wn = warp & 1;
    int qr = lane >> 2, qc = lane & 3;
    int c = t & 3, rb = t >> 2;          // fetch coords

    // A row pointers (already offset by c)
    const float* arow[4];
#pragma unroll
    for (int j = 0; j < 4; j++) {
        int r = row0 + rb + 32 * j;
        arow[j] = (r < cnt) ? (x + (size_t)g_tok[e][r] * Hd + c) : nullptr;
    }
    // B fetch bases: element B[(kk+c+4i)*Ff + col0 + n]
    const float* bgb = Bg + (size_t)c * Ff + col0;
    const float* bub = Bu + (size_t)c * Ff + col0;

    float accG[4][4][4], accU[4][4][4];
#pragma unroll
    for (int a = 0; a < 4; a++)
#pragma unroll
        for (int b = 0; b < 4; b++)
#pragma unroll
            for (int d = 0; d < 4; d++) { accG[a][b][d] = 0.f; accU[a][b][d] = 0.f; }

    float4 la[4], lg[2], lu[2];

    auto fetch = [&](int kk) {
#pragma unroll
        for (int j = 0; j < 4; j++)
            la[j] = arow[j] ? make_float4(arow[j][kk], arow[j][kk + 4], arow[j][kk + 8], arow[j][kk + 12])
                            : make_float4(0, 0, 0, 0);
#pragma unroll
        for (int j = 0; j < 2; j++) {
            int n = rb + 32 * j;
            const float* p0 = bgb + (size_t)kk * Ff + n;
            lg[j] = make_float4(p0[0], p0[(size_t)4 * Ff], p0[(size_t)8 * Ff], p0[(size_t)12 * Ff]);
            const float* p1 = bub + (size_t)kk * Ff + n;
            lu[j] = make_float4(p1[0], p1[(size_t)4 * Ff], p1[(size_t)8 * Ff], p1[(size_t)12 * Ff]);
        }
    };
    auto stage = [&](int buf) {
#pragma unroll
        for (int j = 0; j < 4; j++)
            *(float4*)&sA[buf][rb + 32 * j][4 * c] = tf4(la[j]);
#pragma unroll
        for (int j = 0; j < 2; j++) {
            *(float4*)&sG[buf][rb + 32 * j][4 * c] = tf4(lg[j]);
            *(float4*)&sU[buf][rb + 32 * j][4 * c] = tf4(lu[j]);
        }
    };

    fetch(0); stage(0);
    __syncthreads();
    const int KT = Hd / 16;
    for (int kt = 0; kt < KT; kt++) {
        int buf = kt & 1;
        if (kt + 1 < KT) fetch((kt + 1) * 16);

        float4 alo[4], ahi[4];
#pragma unroll
        for (int mt = 0; mt < 4; mt++) {
            alo[mt] = *(const float4*)&sA[buf][wm * 64 + mt * 16 + qr][4 * qc];
            ahi[mt] = *(const float4*)&sA[buf][wm * 64 + mt * 16 + qr + 8][4 * qc];
        }
#pragma unroll
        for (int nt = 0; nt < 4; nt++) {
            float4 bg = *(const float4*)&sG[buf][wn * 32 + nt * 8 + qr][4 * qc];
            float4 bu = *(const float4*)&sU[buf][wn * 32 + nt * 8 + qr][4 * qc];
            unsigned bg0[2] = { __float_as_uint(bg.x), __float_as_uint(bg.y) };
            unsigned bg1[2] = { __float_as_uint(bg.z), __float_as_uint(bg.w) };
            unsigned bu0[2] = { __float_as_uint(bu.x), __float_as_uint(bu.y) };
            unsigned bu1[2] = { __float_as_uint(bu.z), __float_as_uint(bu.w) };
#pragma unroll
            for (int mt = 0; mt < 4; mt++) {
                unsigned a0[4] = { __float_as_uint(alo[mt].x), __float_as_uint(ahi[mt].x),
                                   __float_as_uint(alo[mt].y), __float_as_uint(ahi[mt].y) };
                unsigned a1[4] = { __float_as_uint(alo[mt].z), __float_as_uint(ahi[mt].z),
                                   __float_as_uint(alo[mt].w), __float_as_uint(ahi[mt].w) };
                mma8(accG[mt][nt], a0, bg0);
                mma8(accG[mt][nt], a1, bg1);
                mma8(accU[mt][nt], a0, bu0);
                mma8(accU[mt][nt], a1, bu1);
            }
        }
        if (kt + 1 < KT) stage(buf ^ 1);
        __syncthreads();
    }

    // epilogue: h = silu(g) * u -> g_h[tok*2+slot]
#pragma unroll
    for (int mt = 0; mt < 4; mt++) {
#pragma unroll
        for (int half = 0; half < 2; half++) {
            int r = row0 + wm * 64 + mt * 16 + qr + half * 8;
            if (r < cnt) {
                int aid = g_tok[e][r] * 2 + g_slot[e][r];
                float* hrow = g_h + (size_t)aid * Ff + col0;
#pragma unroll
                for (int nt = 0; nt < 4; nt++) {
                    float gg0 = accG[mt][nt][half * 2 + 0], gg1 = accG[mt][nt][half * 2 + 1];
                    float uu0 = accU[mt][nt][half * 2 + 0], uu1 = accU[mt][nt][half * 2 + 1];
                    float h0 = gg0 * uu0 / (1.f + __expf(-gg0));
                    float h1 = gg1 * uu1 / (1.f + __expf(-gg1));
                    int cc = wn * 32 + nt * 8 + 2 * qc;
                    *(float2*)(hrow + cc) = make_float2(h0, h1);
                }
            }
        }
    }
}

// ============================================================================
// GEMM2: block 128(M) x 128(N), BK=16, 128 threads, 4 warps 2x2, warp tile 64x64.
// out_slot[tok] = w * (h[aid] @ Wd)
// ============================================================================
__global__ void __launch_bounds__(128) gemm2_kernel(const float* __restrict__ w_down)
{
    int e = blockIdx.z;
    int cnt = g_cnt[e];
    int row0 = blockIdx.y * 128;
    if (row0 >= cnt) return;
    int col0 = blockIdx.x * 128;
    const float* Bd = w_down + (size_t)e * Ff * Hd;

    __shared__ __align__(16) float sA[2][128][16];
    __shared__ __align__(16) float sB[2][128][16];

    int t = threadIdx.x;
    int lane = t & 31, warp = t >> 5;
    int wm = warp >> 1, wn = warp & 1;
    int qr = lane >> 2, qc = lane & 3;
    int c = t & 3, rb = t >> 2;

    const float* arow[4];
#pragma unroll
    for (int j = 0; j < 4; j++) {
        int r = row0 + rb + 32 * j;
        if (r < cnt) {
            int aid = g_tok[e][r] * 2 + g_slot[e][r];
            arow[j] = g_h + (size_t)aid * Ff + c;
        } else arow[j] = nullptr;
    }
    const float* bdb = Bd + (size_t)c * Hd + col0;

    float acc[4][8][4];
#pragma unroll
    for (int a = 0; a < 4; a++)
#pragma unroll
        for (int b = 0; b < 8; b++)
#pragma unroll
            for (int d = 0; d < 4; d++) acc[a][b][d] = 0.f;

    float4 la[4], lb[4];
    auto fetch = [&](int kk) {
#pragma unroll
        for (int j = 0; j < 4; j++)
            la[j] = arow[j] ? make_float4(arow[j][kk], arow[j][kk + 4], arow[j][kk + 8], arow[j][kk + 12])
                            : make_float4(0, 0, 0, 0);
#pragma unroll
        for (int j = 0; j < 4; j++) {
            int n = rb + 32 * j;
            const float* p = bdb + (size_t)kk * Hd + n;
            lb[j] = make_float4(p[0], p[(size_t)4 * Hd], p[(size_t)8 * Hd], p[(size_t)12 * Hd]);
        }
    };
    auto stage = [&](int buf) {
#pragma unroll
        for (int j = 0; j < 4; j++)
            *(float4*)&sA[buf][rb + 32 * j][4 * c] = tf4(la[j]);
#pragma unroll
        for (int j = 0; j < 4; j++)
            *(float4*)&sB[buf][rb + 32 * j][4 * c] = tf4(lb[j]);
    };

    fetch(0); stage(0);
    __syncthreads();
    const int KT = Ff / 16;
    for (int kt = 0; kt < KT; kt++) {
        int buf = kt & 1;
        if (kt + 1 < KT) fetch((kt + 1) * 16);

        float4 alo[4], ahi[4];
#pragma unroll
        for (int mt = 0; mt < 4; mt++) {
            alo[mt] = *(const float4*)&sA[buf][wm * 64 + mt * 16 + qr][4 * qc];
            ahi[mt] = *(const float4*)&sA[buf][wm * 64 + mt * 16 + qr + 8][4 * qc];
        }
#pragma unroll
        for (int nt = 0; nt < 8; nt++) {
            float4 bf = *(const float4*)&sB[buf][wn * 64 + nt * 8 + qr][4 * qc];
            unsigned b0[2] = { __float_as_uint(bf.x), __float_as_uint(bf.y) };
            unsigned b1[2] = { __float_as_uint(bf.z), __float_as_uint(bf.w) };
#pragma unroll
            for (int mt = 0; mt < 4; mt++) {
                unsigned a0[4] = { __float_as_uint(alo[mt].x), __float_as_uint(ahi[mt].x),
                                   __float_as_uint(alo[mt].y), __float_as_uint(ahi[mt].y) };
                unsigned a1[4] = { __float_as_uint(alo[mt].z), __float_as_uint(ahi[mt].z),
                                   __float_as_uint(alo[mt].w), __float_as_uint(ahi[mt].w) };
                mma8(acc[mt][nt], a0, b0);
                mma8(acc[mt][nt], a1, b1);
            }
        }
        if (kt + 1 < KT) stage(buf ^ 1);
        __syncthreads();
    }

#pragma unroll
    for (int mt = 0; mt < 4; mt++) {
#pragma unroll
        for (int half = 0; half < 2; half++) {
            int r = row0 + wm * 64 + mt * 16 + qr + half * 8;
            if (r < cnt) {
                int tok = g_tok[e][r];
                float w = g_wt[e][r];
                int sl  = g_slot[e][r];
                float* orow = g_sbuf + (size_t)sl * NT * Hd + (size_t)tok * Hd + col0;
#pragma unroll
                for (int nt = 0; nt < 8; nt++) {
                    int cc = wn * 64 + nt * 8 + 2 * qc;
                    *(float2*)(orow + cc) = make_float2(w * acc[mt][nt][half * 2 + 0],
                                                        w * acc[mt][nt][half * 2 + 1]);
                }
            }
        }
    }
}

__global__ void combine_kernel(float* __restrict__ out) {
    int i = blockIdx.x * 256 + threadIdx.x;
    if (i < NT * Hd / 4) {
        float4 a = ((const float4*)g_sbuf)[i];
        float4 b = ((const float4*)(g_sbuf + NT * Hd))[i];
        ((float4*)out)[i] = make_float4(a.x + b.x, a.y + b.y, a.z + b.z, a.w + b.w);
    }
}

// ---------------- launch ----------------
extern "C" void kernel_launch(void* const* d_in, const int* in_sizes, int n_in,
                              void* d_out, int out_size) {
    (void)in_sizes; (void)n_in; (void)out_size;
    const float* x      = (const float*)d_in[0];
    const float* gw     = (const float*)d_in[1];
    const float* w_gate = (const float*)d_in[2];
    const float* w_up   = (const float*)d_in[3];
    const float* w_down = (const float*)d_in[4];
    float* out = (float*)d_out;

    zero_kernel<<<1, 32>>>();
    router_kernel<<<NT / 8, 256>>>(x, gw);
    gemm1_kernel<<<dim3(Ff / 64, NT / 128, NE), 128>>>(x, w_gate, w_up);
    gemm2_kernel<<<dim3(Hd / 128, NT / 128, NE), 128>>>(w_down);
    combine_kernel<<<(NT * Hd / 4 + 255) / 256, 256>>>(out);
}